// round 2
// baseline (speedup 1.0000x reference)
#include <cuda_runtime.h>
#include <math.h>

// Problem constants (shapes are fixed by the dataset)
#define NMAX 100000
#define EMAX 1600000

// ---------------- scratch (device globals: no allocations allowed) ----------
__device__ float g_bufA[NMAX * 64];   // h  (node features)
__device__ float g_bufB[NMAX * 64];   // g  (dinv-scaled transformed features)
__device__ float g_dinv[NMAX];
__device__ int   g_cnt[NMAX];         // in-degree (real edges only)
__device__ int   g_rowptr[NMAX + 1];
__device__ int   g_fill[NMAX];
__device__ int   g_col[EMAX];         // src per dst-bucket
__device__ int   g_src[EMAX];
__device__ int   g_dst[EMAX];
__device__ int   g_idx64;             // 1 if edge_index is int64, 0 if int32

// ---------------- edge-index dtype detection + conversion -------------------
// If the buffer holds little-endian int64 values < 2^31, every odd 32-bit word
// is zero. If it holds int32 indices, odd words are random indices (mostly !=0).
__global__ void k_detect(const unsigned* __restrict__ w, int e) {
    // examine first 256 odd words (well within buffer for both interpretations)
    __shared__ int nonzero;
    if (threadIdx.x == 0) nonzero = 0;
    __syncthreads();
    int i = threadIdx.x;                       // 0..255
    if (2 * i + 1 < 2 * e) {
        if (w[2 * i + 1] != 0u) atomicAdd(&nonzero, 1);
    }
    __syncthreads();
    if (threadIdx.x == 0) g_idx64 = (nonzero == 0) ? 1 : 0;
}

__global__ void k_convert(const void* __restrict__ ei, int e, int n) {
    int i = blockIdx.x * blockDim.x + threadIdx.x;
    if (i >= e) return;
    long long s, d;
    if (g_idx64) {
        const long long* p = (const long long*)ei;
        s = p[i]; d = p[(size_t)e + i];
    } else {
        const int* p = (const int*)ei;
        s = p[i]; d = p[(size_t)e + i];
    }
    // defensive clamp: out-of-range becomes a self-edge on node 0 (never traps)
    int si = (s >= 0 && s < n) ? (int)s : 0;
    int di = (d >= 0 && d < n) ? (int)d : 0;
    g_src[i] = si;
    g_dst[i] = di;
}

// ---------------- CSR build ----------------
__global__ void k_init(int n) {
    int i = blockIdx.x * blockDim.x + threadIdx.x;
    if (i < n) g_cnt[i] = 0;
}

__global__ void k_count(int e) {
    int i = blockIdx.x * blockDim.x + threadIdx.x;
    if (i < e) atomicAdd(&g_cnt[g_dst[i]], 1);
}

__global__ void k_dinv(int n) {
    int i = blockIdx.x * blockDim.x + threadIdx.x;
    if (i < n) g_dinv[i] = rsqrtf((float)(g_cnt[i] + 1));   // +1 self loop
}

// single-block exclusive scan of g_cnt -> g_rowptr (chunks of 1024)
__global__ void k_scan(int n) {
    __shared__ int warp_sums[32];
    __shared__ int carry_sh;
    int tid = threadIdx.x;
    int lane = tid & 31, wid = tid >> 5;
    if (tid == 0) { carry_sh = 0; g_rowptr[0] = 0; }
    __syncthreads();
    for (int base = 0; base < n; base += 1024) {
        int i = base + tid;
        int v = (i < n) ? g_cnt[i] : 0;
        int x = v;
        #pragma unroll
        for (int d = 1; d < 32; d <<= 1) {
            int t = __shfl_up_sync(0xffffffffu, x, d);
            if (lane >= d) x += t;
        }
        if (lane == 31) warp_sums[wid] = x;
        __syncthreads();
        if (wid == 0) {
            int s = warp_sums[lane];
            #pragma unroll
            for (int d = 1; d < 32; d <<= 1) {
                int t = __shfl_up_sync(0xffffffffu, s, d);
                if (lane >= d) s += t;
            }
            warp_sums[lane] = s;
        }
        __syncthreads();
        int incl = x + (wid > 0 ? warp_sums[wid - 1] : 0);
        int c = carry_sh;
        if (i < n) g_rowptr[i + 1] = c + incl;
        __syncthreads();
        if (tid == 1023) carry_sh = c + incl;   // incl of last thread = chunk total
        __syncthreads();
    }
}

__global__ void k_initfill(int n) {
    int i = blockIdx.x * blockDim.x + threadIdx.x;
    if (i < n) g_fill[i] = g_rowptr[i];
}

__global__ void k_fill(int e) {
    int i = blockIdx.x * blockDim.x + threadIdx.x;
    if (i < e) {
        int d = g_dst[i];
        int pos = atomicAdd(&g_fill[d], 1);
        if (pos >= 0 && pos < EMAX) g_col[pos] = g_src[i];
    }
}

// ---------------- GEMM: Y = X @ W (+b | *dinv) ----------------
// blockDim = (FOUT, 2); 8 nodes per block, 4 nodes per thread.
// PRE:  in = X param,  out = g_bufA, add bias, no dinv
// !PRE: in = g_bufA,   out = g_bufB, no bias, scale by dinv[row]
template<int FIN, int FOUT, bool PRE>
__launch_bounds__(FOUT * 2)
__global__ void k_gemm(const float* __restrict__ X, const float* __restrict__ W,
                       const float* __restrict__ b, int n)
{
    __shared__ __align__(16) float Ws[FIN * FOUT];
    __shared__ __align__(16) float Xs[8 * FIN];
    const float* __restrict__ in = PRE ? X : g_bufA;
    float* __restrict__ out = PRE ? g_bufA : g_bufB;

    const int T = FOUT * 2;
    int tid = threadIdx.y * FOUT + threadIdx.x;
    #pragma unroll 4
    for (int i = tid; i < FIN * FOUT; i += T) Ws[i] = W[i];

    int node0 = blockIdx.x * 8;
    for (int i = tid; i < 8 * FIN; i += T) {
        int row = node0 + i / FIN;
        Xs[i] = (row < n) ? in[(size_t)node0 * FIN + i] : 0.0f;
    }
    __syncthreads();

    int f = threadIdx.x;
    int y = threadIdx.y;
    float acc0 = 0.f, acc1 = 0.f, acc2 = 0.f, acc3 = 0.f;
    const float* xs = &Xs[(y * 4) * FIN];
    #pragma unroll
    for (int k = 0; k < FIN; k += 4) {
        float4 a0 = *(const float4*)&xs[k];
        float4 a1 = *(const float4*)&xs[FIN + k];
        float4 a2 = *(const float4*)&xs[2 * FIN + k];
        float4 a3 = *(const float4*)&xs[3 * FIN + k];
        float w0 = Ws[(k + 0) * FOUT + f];
        float w1 = Ws[(k + 1) * FOUT + f];
        float w2 = Ws[(k + 2) * FOUT + f];
        float w3 = Ws[(k + 3) * FOUT + f];
        acc0 += a0.x * w0 + a0.y * w1 + a0.z * w2 + a0.w * w3;
        acc1 += a1.x * w0 + a1.y * w1 + a1.z * w2 + a1.w * w3;
        acc2 += a2.x * w0 + a2.y * w1 + a2.z * w2 + a2.w * w3;
        acc3 += a3.x * w0 + a3.y * w1 + a3.z * w2 + a3.w * w3;
    }

    float accs[4] = {acc0, acc1, acc2, acc3};
    float bias_v = PRE ? b[f] : 0.0f;
    #pragma unroll
    for (int j = 0; j < 4; j++) {
        int node = node0 + y * 4 + j;
        if (node < n) {
            float v = accs[j];
            if (PRE) v += bias_v;
            else     v *= g_dinv[node];
            out[(size_t)node * FOUT + f] = v;
        }
    }
}

// ---------------- aggregation: warp per node, register accumulation --------
// out[i] = act( dinv[i] * (g[i] + sum_{src in csr[i]} g[src]) + bias )
template<int FOUT, bool RELU, bool NORM, bool TO_OUT>
__global__ void k_agg(const float* __restrict__ bias, float* __restrict__ Y, int n)
{
    int gw = (int)((blockIdx.x * blockDim.x + threadIdx.x) >> 5);
    int lane = threadIdx.x & 31;
    if (gw >= n) return;
    constexpr int R = FOUT / 32;
    const float* __restrict__ G = g_bufB;
    float* __restrict__ O = TO_OUT ? Y : g_bufA;

    float acc[R];
    const float* gp = G + (size_t)gw * FOUT;
    #pragma unroll
    for (int r = 0; r < R; r++) acc[r] = gp[lane + 32 * r];   // self term

    int s = g_rowptr[gw], e = g_rowptr[gw + 1];
    int j = s;
    for (; j + 3 < e; j += 4) {
        int s0 = g_col[j], s1 = g_col[j + 1], s2 = g_col[j + 2], s3 = g_col[j + 3];
        const float* p0 = G + (size_t)s0 * FOUT;
        const float* p1 = G + (size_t)s1 * FOUT;
        const float* p2 = G + (size_t)s2 * FOUT;
        const float* p3 = G + (size_t)s3 * FOUT;
        #pragma unroll
        for (int r = 0; r < R; r++) {
            float v0 = p0[lane + 32 * r];
            float v1 = p1[lane + 32 * r];
            float v2 = p2[lane + 32 * r];
            float v3 = p3[lane + 32 * r];
            acc[r] += (v0 + v1) + (v2 + v3);
        }
    }
    for (; j < e; j++) {
        int s0 = g_col[j];
        const float* p0 = G + (size_t)s0 * FOUT;
        #pragma unroll
        for (int r = 0; r < R; r++) acc[r] += p0[lane + 32 * r];
    }

    float di = g_dinv[gw];
    float v[R];
    #pragma unroll
    for (int r = 0; r < R; r++) {
        v[r] = di * acc[r] + bias[lane + 32 * r];
        if (RELU) v[r] = fmaxf(v[r], 0.0f);
    }
    if (NORM) {
        float ss = 0.0f;
        #pragma unroll
        for (int r = 0; r < R; r++) ss += v[r] * v[r];
        #pragma unroll
        for (int d = 16; d; d >>= 1) ss += __shfl_xor_sync(0xffffffffu, ss, d);
        float inv = 1.0f / fmaxf(sqrtf(ss), 1e-12f);
        #pragma unroll
        for (int r = 0; r < R; r++) v[r] *= inv;
    }
    #pragma unroll
    for (int r = 0; r < R; r++) O[(size_t)gw * FOUT + lane + 32 * r] = v[r];
}

// ---------------- host ----------------
extern "C" void kernel_launch(void* const* d_in, const int* in_sizes, int n_in,
                              void* d_out, int out_size)
{
    const float* x     = (const float*)d_in[0];
    const void*  ei    = d_in[1];
    const float* W_pre = (const float*)d_in[2];
    const float* b_pre = (const float*)d_in[3];
    const float* W1    = (const float*)d_in[4];
    const float* b1    = (const float*)d_in[5];
    const float* W2    = (const float*)d_in[6];
    const float* b2    = (const float*)d_in[7];
    const float* W3    = (const float*)d_in[8];
    const float* b3    = (const float*)d_in[9];
    float*       out   = (float*)d_out;

    int n = in_sizes[0] / 128;
    int e = in_sizes[1] / 2;

    int nb = (n + 255) / 256;
    int eb = (e + 255) / 256;

    // edge-index parse (dtype-robust) + CSR build + dinv
    k_detect<<<1, 256>>>((const unsigned*)ei, e);
    k_convert<<<eb, 256>>>(ei, e, n);
    k_init<<<nb, 256>>>(n);
    k_count<<<eb, 256>>>(e);
    k_dinv<<<nb, 256>>>(n);
    k_scan<<<1, 1024>>>(n);
    k_initfill<<<nb, 256>>>(n);
    k_fill<<<eb, 256>>>(e);

    int gb = (n + 7) / 8;   // 8 nodes per gemm block, 8 warps per agg block

    // h0 = x @ W_pre + b_pre              -> bufA
    k_gemm<128, 64, true ><<<gb, dim3(64, 2)>>>(x, W_pre, b_pre, n);
    // layer 1
    k_gemm<64, 64, false><<<gb, dim3(64, 2)>>>(x, W1, b1, n);     // bufA->bufB *dinv
    k_agg<64, true, false, false><<<gb, 256>>>(b1, out, n);       // bufB->bufA, relu
    // layer 2
    k_gemm<64, 64, false><<<gb, dim3(64, 2)>>>(x, W2, b2, n);
    k_agg<64, true, false, false><<<gb, 256>>>(b2, out, n);
    // layer 3 + L2 normalize
    k_gemm<64, 32, false><<<gb, dim3(32, 2)>>>(x, W3, b3, n);
    k_agg<32, false, true, true><<<gb, 256>>>(b3, out, n);
}

// round 3
// speedup vs baseline: 1.7401x; 1.7401x over previous
#include <cuda_runtime.h>
#include <math.h>

#define NMAX 100000
#define EMAX 1600000

// ---------------- scratch ----------------
__device__ __align__(16) float g_bufA[NMAX * 64];   // h
__device__ __align__(16) float g_bufB[NMAX * 64];   // g = (h@W)*dinv
__device__ float g_dinv[NMAX];
__device__ int   g_cnt[NMAX];
__device__ int   g_rowptr[NMAX + 1];
__device__ int   g_fill[NMAX];
__device__ int   g_col[EMAX];
__device__ int   g_src[EMAX];
__device__ int   g_dst[EMAX];
__device__ int   g_idx64;
__device__ int   g_bsum[128];
__device__ int   g_boff[128];

// ---------------- edge-index dtype detection + conversion (+count) ---------
__global__ void k_detect(const unsigned* __restrict__ w, int e) {
    __shared__ int nonzero;
    if (threadIdx.x == 0) nonzero = 0;
    __syncthreads();
    int i = threadIdx.x;
    if (2 * i + 1 < 2 * e) {
        if (w[2 * i + 1] != 0u) atomicAdd(&nonzero, 1);
    }
    __syncthreads();
    if (threadIdx.x == 0) g_idx64 = (nonzero == 0) ? 1 : 0;
}

__global__ void k_convert(const void* __restrict__ ei, int e, int n) {
    int i = blockIdx.x * blockDim.x + threadIdx.x;
    if (i >= e) return;
    long long s, d;
    if (g_idx64) {
        const long long* p = (const long long*)ei;
        s = p[i]; d = p[(size_t)e + i];
    } else {
        const int* p = (const int*)ei;
        s = p[i]; d = p[(size_t)e + i];
    }
    int si = (s >= 0 && s < n) ? (int)s : 0;
    int di = (d >= 0 && d < n) ? (int)d : 0;
    g_src[i] = si;
    g_dst[i] = di;
    atomicAdd(&g_cnt[di], 1);
}

// ---------------- 3-phase scan + finalize (dinv, fill init) -----------------
__global__ void k_scan1(int n) {
    __shared__ int ws[32];
    int i = blockIdx.x * 1024 + threadIdx.x;
    int lane = threadIdx.x & 31, wid = threadIdx.x >> 5;
    int v = (i < n) ? g_cnt[i] : 0;
    int x = v;
    #pragma unroll
    for (int d = 1; d < 32; d <<= 1) {
        int t = __shfl_up_sync(0xffffffffu, x, d);
        if (lane >= d) x += t;
    }
    if (lane == 31) ws[wid] = x;
    __syncthreads();
    if (wid == 0) {
        int s = ws[lane];
        #pragma unroll
        for (int d = 1; d < 32; d <<= 1) {
            int t = __shfl_up_sync(0xffffffffu, s, d);
            if (lane >= d) s += t;
        }
        ws[lane] = s;
    }
    __syncthreads();
    int incl = x + (wid ? ws[wid - 1] : 0);
    if (i < n) g_rowptr[i + 1] = incl;
    if (threadIdx.x == 1023) g_bsum[blockIdx.x] = incl;
}

__global__ void k_scan2(int nb) {
    __shared__ int sm[128];
    int t = threadIdx.x;
    int v = (t < nb) ? g_bsum[t] : 0;
    sm[t] = v;
    __syncthreads();
    #pragma unroll
    for (int d = 1; d < 128; d <<= 1) {
        int a = (t >= d) ? sm[t - d] : 0;
        __syncthreads();
        sm[t] += a;
        __syncthreads();
    }
    g_boff[t] = sm[t] - v;   // exclusive
}

__global__ void k_scan3(int n) {
    int i = blockIdx.x * 1024 + threadIdx.x;
    if (i >= n) return;
    int boff = g_boff[blockIdx.x];
    int v = g_rowptr[i + 1] + boff;
    g_rowptr[i + 1] = v;
    int c = g_cnt[i];
    g_fill[i] = v - c;
    g_dinv[i] = rsqrtf((float)(c + 1));
    if (i == 0) g_rowptr[0] = 0;
}

__global__ void k_fill(int e) {
    int i = blockIdx.x * blockDim.x + threadIdx.x;
    if (i < e) {
        int pos = atomicAdd(&g_fill[g_dst[i]], 1);
        if (pos >= 0 && pos < EMAX) g_col[pos] = g_src[i];
    }
}

// ---------------- GEMM: out = in @ W (+b | *dinv) ---------------------------
// 256 threads. FT f-threads x NT node-threads; 4x4 register tile per thread.
// f = fx + FT*j (interleaved -> conflict-free Wt reads), node = node0 + nx + NT*i.
template<int FIN, int FOUT, bool PRE, int NODES, int FT>
__launch_bounds__(256)
__global__ void k_gemm(const float* __restrict__ X, const float* __restrict__ W,
                       const float* __restrict__ b, int n)
{
    constexpr int NT = 256 / FT;
    constexpr int RS = FIN + 4;
    extern __shared__ float sm[];
    float* Wt = sm;               // [FOUT][RS]  (transposed W)
    float* Xs = sm + FOUT * RS;   // [NODES][RS]

    const float* __restrict__ in = PRE ? X : g_bufA;
    float* __restrict__ out = PRE ? g_bufA : g_bufB;

    int tid = threadIdx.x;
    for (int i = tid; i < FIN * FOUT; i += 256) {
        int k = i / FOUT, f = i % FOUT;
        Wt[f * RS + k] = W[i];
    }
    int node0 = blockIdx.x * NODES;
    for (int i = tid; i < NODES * FIN / 4; i += 256) {
        int row = (i * 4) / FIN;
        int col = (i * 4) % FIN;
        int nd = node0 + row;
        float4 v = (nd < n) ? *(const float4*)&in[(size_t)nd * FIN + col]
                            : make_float4(0.f, 0.f, 0.f, 0.f);
        *(float4*)&Xs[row * RS + col] = v;
    }
    __syncthreads();

    int fx = tid % FT;
    int nx = tid / FT;
    float acc[4][4];
    #pragma unroll
    for (int i = 0; i < 4; i++)
        #pragma unroll
        for (int j = 0; j < 4; j++) acc[i][j] = 0.f;

    const float* xb = Xs + nx * RS;
    const float* wb = Wt + fx * RS;
    #pragma unroll
    for (int k = 0; k < FIN; k += 4) {
        float4 xv[4], wv[4];
        #pragma unroll
        for (int i = 0; i < 4; i++) xv[i] = *(const float4*)(xb + i * NT * RS + k);
        #pragma unroll
        for (int j = 0; j < 4; j++) wv[j] = *(const float4*)(wb + j * FT * RS + k);
        #pragma unroll
        for (int i = 0; i < 4; i++)
            #pragma unroll
            for (int j = 0; j < 4; j++) {
                acc[i][j] += xv[i].x * wv[j].x;
                acc[i][j] += xv[i].y * wv[j].y;
                acc[i][j] += xv[i].z * wv[j].z;
                acc[i][j] += xv[i].w * wv[j].w;
            }
    }

    #pragma unroll
    for (int i = 0; i < 4; i++) {
        int nd = node0 + nx + NT * i;
        if (nd < n) {
            float scale = PRE ? 1.0f : g_dinv[nd];
            #pragma unroll
            for (int j = 0; j < 4; j++) {
                int f = fx + FT * j;
                float v = acc[i][j];
                v = PRE ? (v + b[f]) : (v * scale);
                out[(size_t)nd * FOUT + f] = v;
            }
        }
    }
}

// ---------------- aggregation ------------------------------------------------
// warp per node; LPG = FOUT/4 lanes per edge-group, NG = 32/LPG groups in flight.
// out[i] = act( dinv[i]*(g[i] + sum_{src} g[src]) + bias ), optional L2-norm.
template<int FOUT, bool RELU, bool NORM, bool TO_OUT>
__global__ void k_agg(const float* __restrict__ bias, float* __restrict__ Y, int n)
{
    constexpr int LPG = FOUT / 4;
    constexpr int NG = 32 / LPG;
    int node = (int)((blockIdx.x * blockDim.x + threadIdx.x) >> 5);
    if (node >= n) return;
    int lane = threadIdx.x & 31;
    int g = lane / LPG;
    int fl = lane % LPG;
    const float* __restrict__ G = g_bufB;
    float* __restrict__ O = TO_OUT ? Y : g_bufA;

    float4 acc = make_float4(0.f, 0.f, 0.f, 0.f);
    if (g == 0) acc = *(const float4*)(G + (size_t)node * FOUT + fl * 4);  // self

    int s = g_rowptr[node], e = g_rowptr[node + 1];
    int j = s + g;
    for (; j + NG < e; j += 2 * NG) {
        int c0 = g_col[j];
        int c1 = g_col[j + NG];
        float4 v0 = *(const float4*)(G + (size_t)c0 * FOUT + fl * 4);
        float4 v1 = *(const float4*)(G + (size_t)c1 * FOUT + fl * 4);
        acc.x += v0.x + v1.x;
        acc.y += v0.y + v1.y;
        acc.z += v0.z + v1.z;
        acc.w += v0.w + v1.w;
    }
    if (j < e) {
        int c0 = g_col[j];
        float4 v0 = *(const float4*)(G + (size_t)c0 * FOUT + fl * 4);
        acc.x += v0.x; acc.y += v0.y; acc.z += v0.z; acc.w += v0.w;
    }

    // combine groups
    #pragma unroll
    for (int d = LPG; d < 32; d <<= 1) {
        acc.x += __shfl_xor_sync(0xffffffffu, acc.x, d);
        acc.y += __shfl_xor_sync(0xffffffffu, acc.y, d);
        acc.z += __shfl_xor_sync(0xffffffffu, acc.z, d);
        acc.w += __shfl_xor_sync(0xffffffffu, acc.w, d);
    }

    float di = g_dinv[node];
    float4 bv = *(const float4*)(bias + fl * 4);
    float4 v;
    v.x = di * acc.x + bv.x;
    v.y = di * acc.y + bv.y;
    v.z = di * acc.z + bv.z;
    v.w = di * acc.w + bv.w;
    if (RELU) {
        v.x = fmaxf(v.x, 0.f); v.y = fmaxf(v.y, 0.f);
        v.z = fmaxf(v.z, 0.f); v.w = fmaxf(v.w, 0.f);
    }
    if (NORM) {
        float ss = v.x * v.x + v.y * v.y + v.z * v.z + v.w * v.w;
        #pragma unroll
        for (int d = 1; d < LPG; d <<= 1) ss += __shfl_xor_sync(0xffffffffu, ss, d);
        float inv = 1.0f / fmaxf(sqrtf(ss), 1e-12f);
        v.x *= inv; v.y *= inv; v.z *= inv; v.w *= inv;
    }
    if (g == 0) *(float4*)(O + (size_t)node * FOUT + fl * 4) = v;
}

// ---------------- host ----------------
extern "C" void kernel_launch(void* const* d_in, const int* in_sizes, int n_in,
                              void* d_out, int out_size)
{
    const float* x     = (const float*)d_in[0];
    const void*  ei    = d_in[1];
    const float* W_pre = (const float*)d_in[2];
    const float* b_pre = (const float*)d_in[3];
    const float* W1    = (const float*)d_in[4];
    const float* b1    = (const float*)d_in[5];
    const float* W2    = (const float*)d_in[6];
    const float* b2    = (const float*)d_in[7];
    const float* W3    = (const float*)d_in[8];
    const float* b3    = (const float*)d_in[9];
    float*       out   = (float*)d_out;

    int n = in_sizes[0] / 128;
    int e = in_sizes[1] / 2;
    int eb = (e + 255) / 256;
    int sb = (n + 1023) / 1024;

    // dynamic smem sizes
    const int smem_pre = (64 * (128 + 4) + 64 * (128 + 4)) * 4;   // 67584
    const int smem_mid = (64 * (64 + 4) + 64 * (64 + 4)) * 4;     // 34816
    const int smem_out = (32 * (64 + 4) + 128 * (64 + 4)) * 4;    // 43520
    cudaFuncSetAttribute(k_gemm<128, 64, true, 64, 16>,
                         cudaFuncAttributeMaxDynamicSharedMemorySize, smem_pre);
    cudaFuncSetAttribute(k_gemm<64, 64, false, 64, 16>,
                         cudaFuncAttributeMaxDynamicSharedMemorySize, smem_mid);
    cudaFuncSetAttribute(k_gemm<64, 32, false, 128, 8>,
                         cudaFuncAttributeMaxDynamicSharedMemorySize, smem_out);

    // CSR build
    void* cntp = nullptr;
    cudaGetSymbolAddress(&cntp, g_cnt);
    cudaMemsetAsync(cntp, 0, (size_t)n * sizeof(int));
    k_detect<<<1, 256>>>((const unsigned*)ei, e);
    k_convert<<<eb, 256>>>(ei, e, n);
    k_scan1<<<sb, 1024>>>(n);
    k_scan2<<<1, 128>>>(sb);
    k_scan3<<<sb, 1024>>>(n);
    k_fill<<<eb, 256>>>(e);

    int gb64  = (n + 63) / 64;
    int gb128 = (n + 127) / 128;
    int ab    = (n + 7) / 8;     // 8 warps (nodes) per 256-thread agg block

    // pre: h0 = x @ W_pre + b_pre  -> bufA
    k_gemm<128, 64, true, 64, 16><<<gb64, 256, smem_pre>>>(x, W_pre, b_pre, n);
    // layer 1
    k_gemm<64, 64, false, 64, 16><<<gb64, 256, smem_mid>>>(x, W1, b1, n);
    k_agg<64, true, false, false><<<ab, 256>>>(b1, out, n);
    // layer 2
    k_gemm<64, 64, false, 64, 16><<<gb64, 256, smem_mid>>>(x, W2, b2, n);
    k_agg<64, true, false, false><<<ab, 256>>>(b2, out, n);
    // layer 3 + L2 normalize
    k_gemm<64, 32, false, 128, 8><<<gb128, 256, smem_out>>>(x, W3, b3, n);
    k_agg<32, false, true, true><<<ab, 256>>>(b3, out, n);
}